// round 12
// baseline (speedup 1.0000x reference)
#include <cuda_runtime.h>
#include <math.h>

// Problem: B=64, V=8, J=17, H=256
// keypoints_gt: (B,V,J,2) float32   -> d_in[0], 17408 elems
// heatmap:      (B,V,1,H,H) float32 -> d_in[1], 33554432 elems
// out: scalar float = mean over B*V*J of -log(hm[b,v, clip(ceil(ky)), clip(ceil(kx))])
//
// Design: 272 uniform single-warp worker CTAs (max latency overlap, no smem,
// no __syncthreads) + 1 dedicated poller CTA that spins from dispatch.
// Partials double as completion flags (-log(val) > 0 strictly, so 0.0f is an
// unreachable sentinel). Poller sums in a fixed order (deterministic) and
// rearms the sentinels for the next graph replay.

#define NTOT   8704      // 64*8*17
#define JDIM   17
#define HDIM   256
#define NWRK   272       // worker blocks: 272 * 32 = 8704 exactly
#define NBLK   (NWRK + 1) // + dedicated poller block
#define NTHR   32

__device__ float g_partials[NWRK];   // zero-init at load; poller rearms each call

__device__ __forceinline__ float4 ld_relaxed_v4(const float4* p) {
    float4 v;
    asm volatile("ld.relaxed.gpu.global.v4.f32 {%0,%1,%2,%3}, [%4];"
                 : "=f"(v.x), "=f"(v.y), "=f"(v.z), "=f"(v.w)
                 : "l"(p) : "memory");
    return v;
}
__device__ __forceinline__ void st_relaxed(float* p, float v) {
    asm volatile("st.relaxed.gpu.global.f32 [%0], %1;" :: "l"(p), "f"(v) : "memory");
}

__global__ __launch_bounds__(NTHR) void heatmap_ce_fused_kernel(
    const float* __restrict__ kp,   // (NTOT, 2)
    const float* __restrict__ hm,   // (B*V, H, H)
    float* __restrict__ out)
{
    const int lane = threadIdx.x;                     // block == warp

    if (blockIdx.x < NWRK) {
        // ---------------- worker path: fully uniform ----------------
        const int i = blockIdx.x * NTHR + lane;       // 0..8703, exact

        // kp-independent base, overlaps kp load latency.
        // Max offset 64*8*65536 = 33.5M < 2^31 -> 32-bit address math.
        const int base = (i / JDIM) * (HDIM * HDIM);  // bv * 65536

        const float2 k = reinterpret_cast<const float2*>(kp)[i];

        int xi = (int)ceilf(k.x);
        int yi = (int)ceilf(k.y);
        xi = min(max(xi, 0), HDIM - 1);
        yi = min(max(yi, 0), HDIM - 1);
        const int off = base + (yi << 8) + xi;

        const float val = __ldg(hm + off);
        float s = -__logf(val);   // strictly > 0; fast log well within 1e-3 tol

        #pragma unroll
        for (int o = 16; o > 0; o >>= 1)
            s += __shfl_down_sync(0xFFFFFFFFu, s, o);

        if (lane == 0)
            st_relaxed(&g_partials[blockIdx.x], s);   // value IS the flag
        return;
    }

    // ---------------- dedicated poller: spins from dispatch ----------------
    // 272 partials = 68 float4. lane owns f4 idx: lane, lane+32; lanes 0..3 +64.
    const float4* p4 = reinterpret_cast<const float4*>(g_partials);
    float4 a, b, c;
    bool da = false, db = false, dc = (lane >= 68 - 64);
    c = make_float4(0.f, 0.f, 0.f, 0.f);
    while (true) {
        if (!da) { a = ld_relaxed_v4(&p4[lane]);
                   da = (a.x != 0.f) & (a.y != 0.f) & (a.z != 0.f) & (a.w != 0.f); }
        if (!db) { b = ld_relaxed_v4(&p4[lane + 32]);
                   db = (b.x != 0.f) & (b.y != 0.f) & (b.z != 0.f) & (b.w != 0.f); }
        if (!dc) { c = ld_relaxed_v4(&p4[lane + 64]);
                   dc = (c.x != 0.f) & (c.y != 0.f) & (c.z != 0.f) & (c.w != 0.f); }
        if (__all_sync(0xFFFFFFFFu, da && db && dc)) break;
    }

    // Rearm sentinels immediately — values live in registers; these STGs
    // overlap the shfl-reduce dependency chain below.
    float4* q4 = reinterpret_cast<float4*>(g_partials);
    const float4 z = make_float4(0.f, 0.f, 0.f, 0.f);
    q4[lane]      = z;
    q4[lane + 32] = z;
    if (lane < 68 - 64) q4[lane + 64] = z;

    // fixed-order pairwise summation (deterministic)
    float s2 = ((a.x + a.y) + (a.z + a.w))
             + (((b.x + b.y) + (b.z + b.w))
             +  ((c.x + c.y) + (c.z + c.w)));
    #pragma unroll
    for (int o = 16; o > 0; o >>= 1)
        s2 += __shfl_down_sync(0xFFFFFFFFu, s2, o);

    if (lane == 0)
        out[0] = s2 * (1.0f / (float)NTOT);
}

extern "C" void kernel_launch(void* const* d_in, const int* in_sizes, int n_in,
                              void* d_out, int out_size)
{
    const float* kp = (const float*)d_in[0];
    const float* hm = (const float*)d_in[1];
    float* out = (float*)d_out;

    heatmap_ce_fused_kernel<<<NBLK, NTHR>>>(kp, hm, out);
}